// round 1
// baseline (speedup 1.0000x reference)
#include <cuda_runtime.h>
#include <cuda_bf16.h>

// Problem constants
#define NB    4
#define CIN   512
#define HH    128
#define WW    128
#define HWSZ  16384
#define LOG2HW 14
#define KCLS  19
#define KC    256
#define OUTC  512
#define MTOT  (NB * HWSZ)   // 65536

static __device__ float g_p[NB * KCLS * HWSZ];          // softmax probs
static __device__ float g_proxy[NB * CIN * KCLS];       // (n, c, k)
static __device__ float g_kk[NB * KC * KCLS];           // (n, kc, k)
static __device__ float g_val[NB * KCLS * KC];          // (n, k, kc)
static __device__ float g_buf1[(size_t)MTOT * KC];      // q1, then ctx   (m, kc)
static __device__ float g_q[(size_t)MTOT * KC];         // q              (m, kc)
static __device__ float g_u[(size_t)MTOT * CIN];        // upsampled ctx  (m, c)

__device__ __forceinline__ float relu_(float x) { return fmaxf(x, 0.0f); }

// ---------------------------------------------------------------------------
// Kernel 1: softmax of probs over spatial dim. One block per (n,k) row.
// ---------------------------------------------------------------------------
__global__ __launch_bounds__(256)
void softmax_p_kernel(const float* __restrict__ probs, float* __restrict__ p)
{
    int row = blockIdx.x;                 // 0..NB*KCLS-1
    const float* src = probs + (size_t)row * HWSZ;
    float*       dst = p     + (size_t)row * HWSZ;
    int tid = threadIdx.x;
    __shared__ float red[256];

    // max
    float m = -1e30f;
    for (int i = tid; i < HWSZ; i += 256) m = fmaxf(m, src[i]);
    red[tid] = m; __syncthreads();
    for (int s = 128; s > 0; s >>= 1) {
        if (tid < s) red[tid] = fmaxf(red[tid], red[tid + s]);
        __syncthreads();
    }
    m = red[0]; __syncthreads();

    // sum exp
    float sum = 0.0f;
    for (int i = tid; i < HWSZ; i += 256) sum += __expf(src[i] - m);
    red[tid] = sum; __syncthreads();
    for (int s = 128; s > 0; s >>= 1) {
        if (tid < s) red[tid] += red[tid + s];
        __syncthreads();
    }
    float inv = 1.0f / red[0];

    for (int i = tid; i < HWSZ; i += 256) dst[i] = __expf(src[i] - m) * inv;
}

// ---------------------------------------------------------------------------
// Kernel 2: proxy[n,c,k] = sum_s p[n,k,s] * feats[n,c,s].
// One block handles (n, 4 channels). 256 threads split the s loop.
// ---------------------------------------------------------------------------
__global__ __launch_bounds__(256)
void proxy_kernel(const float* __restrict__ feats, const float* __restrict__ p,
                  float* __restrict__ proxy)
{
    int b  = blockIdx.x;                  // NB * CIN/4 blocks
    int n  = b / (CIN / 4);
    int c0 = (b % (CIN / 4)) * 4;
    int tid = threadIdx.x;

    float acc[4][KCLS];
#pragma unroll
    for (int cc = 0; cc < 4; cc++)
#pragma unroll
        for (int k = 0; k < KCLS; k++) acc[cc][k] = 0.0f;

    const float* pb = p     + (size_t)n * KCLS * HWSZ;
    const float* fb = feats + ((size_t)n * CIN + c0) * HWSZ;

    for (int s = tid; s < HWSZ; s += 256) {
        float pv[KCLS];
#pragma unroll
        for (int k = 0; k < KCLS; k++) pv[k] = pb[k * HWSZ + s];
#pragma unroll
        for (int cc = 0; cc < 4; cc++) {
            float f = fb[cc * HWSZ + s];
#pragma unroll
            for (int k = 0; k < KCLS; k++) acc[cc][k] += f * pv[k];
        }
    }

    __shared__ float red[8][80];
    int lane = tid & 31, wp = tid >> 5;
#pragma unroll
    for (int cc = 0; cc < 4; cc++)
#pragma unroll
        for (int k = 0; k < KCLS; k++) {
            float v = acc[cc][k];
            v += __shfl_down_sync(0xffffffffu, v, 16);
            v += __shfl_down_sync(0xffffffffu, v, 8);
            v += __shfl_down_sync(0xffffffffu, v, 4);
            v += __shfl_down_sync(0xffffffffu, v, 2);
            v += __shfl_down_sync(0xffffffffu, v, 1);
            if (lane == 0) red[wp][cc * KCLS + k] = v;
        }
    __syncthreads();
    if (tid < 4 * KCLS) {
        float s2 = 0.0f;
#pragma unroll
        for (int w2 = 0; w2 < 8; w2++) s2 += red[w2][tid];
        int cc = tid / KCLS, k = tid % KCLS;
        proxy[((size_t)n * CIN + c0 + cc) * KCLS + k] = s2;
    }
}

// ---------------------------------------------------------------------------
// Kernel 3: object branch. One block per (n,k). Computes:
//   h1 = cbr(proxy_col, wo1), kk = cbr(h1, wo2), val = cbr(proxy_col, wd)
// ---------------------------------------------------------------------------
__global__ __launch_bounds__(256)
void obj_kernel(const float* __restrict__ proxy,
                const float* __restrict__ wo1, const float* __restrict__ bo1,
                const float* __restrict__ so1, const float* __restrict__ to1,
                const float* __restrict__ wo2, const float* __restrict__ bo2,
                const float* __restrict__ so2, const float* __restrict__ to2,
                const float* __restrict__ wd,  const float* __restrict__ bd,
                const float* __restrict__ sd,  const float* __restrict__ td,
                float* __restrict__ kkout, float* __restrict__ valout)
{
    int n = blockIdx.x / KCLS, k = blockIdx.x % KCLS;
    int tid = threadIdx.x;   // 256
    __shared__ float col[CIN];
    __shared__ float h1[KC];

    const float* pc = proxy + (size_t)n * CIN * KCLS + k;
    col[tid]       = pc[(size_t)tid * KCLS];
    col[tid + 256] = pc[(size_t)(tid + 256) * KCLS];
    __syncthreads();

    float a1 = 0.0f, av = 0.0f;
    const float* w1 = wo1 + (size_t)tid * CIN;
    const float* wv = wd  + (size_t)tid * CIN;
#pragma unroll 4
    for (int c = 0; c < CIN; c++) {
        float x = col[c];
        a1 += x * w1[c];
        av += x * wv[c];
    }
    a1 = relu_((a1 + bo1[tid]) * so1[tid] + to1[tid]);
    av = relu_((av + bd[tid])  * sd[tid]  + td[tid]);
    valout[((size_t)n * KCLS + k) * KC + tid] = av;
    h1[tid] = a1;
    __syncthreads();

    float a2 = 0.0f;
    const float* w2 = wo2 + (size_t)tid * KC;
#pragma unroll 4
    for (int c = 0; c < KC; c++) a2 += h1[c] * w2[c];
    a2 = relu_((a2 + bo2[tid]) * so2[tid] + to2[tid]);
    kkout[((size_t)n * KC + tid) * KCLS + k] = a2;
}

// ---------------------------------------------------------------------------
// Kernel 4: attention. One block = 64 pixels. logits(64x19) -> softmax ->
// ctx(64x256). kk kept in smem; q streamed through smem chunks; val from L2.
// ---------------------------------------------------------------------------
__global__ __launch_bounds__(256)
void attn_kernel(const float* __restrict__ q, const float* __restrict__ kk,
                 const float* __restrict__ val, float* __restrict__ ctx)
{
    int m0 = blockIdx.x * 64;
    int n  = m0 >> LOG2HW;
    int tid = threadIdx.x;

    __shared__ float kks[KC][KCLS];      // kk[n, kc, k]
    __shared__ float qs[64][33];
    __shared__ float sims[64][20];

    const float* kkb = kk + (size_t)n * KC * KCLS;
    for (int i = tid; i < KC * KCLS; i += 256) {
        kks[i / KCLS][i % KCLS] = kkb[i];
    }
    __syncthreads();

    int i = tid & 63;
    int g = tid >> 6;                    // 0..3
    float acc[5];
#pragma unroll
    for (int z = 0; z < 5; z++) acc[z] = 0.0f;

    for (int kc0 = 0; kc0 < KC; kc0 += 32) {
        // load q chunk 64x32 (float4 per thread, two rows)
        int r  = tid >> 3;
        int c4 = (tid & 7) * 4;
#pragma unroll
        for (int rr = 0; rr < 2; rr++) {
            float4 v = *(const float4*)&q[(size_t)(m0 + r + rr * 32) * KC + kc0 + c4];
            qs[r + rr * 32][c4 + 0] = v.x;
            qs[r + rr * 32][c4 + 1] = v.y;
            qs[r + rr * 32][c4 + 2] = v.z;
            qs[r + rr * 32][c4 + 3] = v.w;
        }
        __syncthreads();
#pragma unroll 8
        for (int kc = 0; kc < 32; kc++) {
            float a = qs[i][kc];
#pragma unroll
            for (int z = 0; z < 5; z++) {
                int k = g + z * 4;
                if (k < KCLS) acc[z] += a * kks[kc0 + kc][k];
            }
        }
        __syncthreads();
    }

#pragma unroll
    for (int z = 0; z < 5; z++) {
        int k = g + z * 4;
        if (k < KCLS) sims[i][k] = acc[z] * 0.0625f;   // KC^-0.5 = 1/16
    }
    __syncthreads();

    if (tid < 64) {
        float m = -1e30f;
#pragma unroll
        for (int k = 0; k < KCLS; k++) m = fmaxf(m, sims[tid][k]);
        float s = 0.0f;
        float e[KCLS];
#pragma unroll
        for (int k = 0; k < KCLS; k++) { e[k] = __expf(sims[tid][k] - m); s += e[k]; }
        float inv = 1.0f / s;
#pragma unroll
        for (int k = 0; k < KCLS; k++) sims[tid][k] = e[k] * inv;
    }
    __syncthreads();

    // ctx[m0+ii, tid] = sum_k sims[ii][k] * val[n, k, tid]
    float vreg[KCLS];
    const float* vb = val + (size_t)n * KCLS * KC + tid;
#pragma unroll
    for (int k = 0; k < KCLS; k++) vreg[k] = vb[k * KC];

    for (int ii = 0; ii < 64; ii++) {
        float a = 0.0f;
#pragma unroll
        for (int k = 0; k < KCLS; k++) a += sims[ii][k] * vreg[k];
        ctx[(size_t)(m0 + ii) * KC + tid] = a;
    }
}

// ---------------------------------------------------------------------------
// Generic SGEMM with fused bias/BN/ReLU epilogue.
//   out = relu((A @ W^T + b) * s + t)
// A is M x Kin.  W is Nout x Kin (row-major).
// AMODE 0: A row-major with leading dim lda.
// AMODE 1: A in channel-major (n, k, s) layout with KtC channels (transposed).
// AMODE 2: k < Ksplit -> row-major A (lda); k >= Ksplit -> channel-major A2 (KtC).
// STORE_T false: out row-major (m, o). true: out channel-major (n, o, s).
// Tile 128x128x16, 256 threads, 8x8 microtile per thread.
// ---------------------------------------------------------------------------
template<int AMODE, bool STORE_T>
__global__ __launch_bounds__(256)
void gemm_cbr(const float* __restrict__ A, const float* __restrict__ A2,
              const float* __restrict__ W,
              const float* __restrict__ bias, const float* __restrict__ sc,
              const float* __restrict__ sh,
              float* __restrict__ out,
              int Nout, int Kin, int Ksplit, int lda, int KtC)
{
    __shared__ float As[16][128];
    __shared__ float Bs[16][128];

    int m0 = blockIdx.x * 128;
    int o0 = blockIdx.y * 128;
    int tid = threadIdx.x;
    int ty = tid >> 4, tx = tid & 15;

    int n  = m0 >> LOG2HW;
    int s0 = m0 & (HWSZ - 1);

    float acc[8][8];
#pragma unroll
    for (int ii = 0; ii < 8; ii++)
#pragma unroll
        for (int jj = 0; jj < 8; jj++) acc[ii][jj] = 0.0f;

    for (int k0 = 0; k0 < Kin; k0 += 16) {
        // ---- load A tile ----
        bool trans = (AMODE == 1) || (AMODE == 2 && k0 >= Ksplit);
        if (trans) {
            const float* src = (AMODE == 2) ? A2 : A;
            int kbase = (AMODE == 2) ? (k0 - Ksplit) : k0;
            int kcol = tid >> 7;          // 0..1
            int srow = tid & 127;
            const float* sp = src + ((size_t)n * KtC + kbase + kcol) * HWSZ + s0 + srow;
#pragma unroll
            for (int kk2 = 0; kk2 < 16; kk2 += 2)
                As[kk2 + kcol][srow] = sp[(size_t)kk2 * HWSZ];
        } else {
            int arow = tid >> 2;          // 0..63
            int ac4  = (tid & 3) * 4;
#pragma unroll
            for (int rr = 0; rr < 2; rr++) {
                int r = arow + rr * 64;
                float4 v = *(const float4*)&A[(size_t)(m0 + r) * lda + k0 + ac4];
                As[ac4 + 0][r] = v.x;
                As[ac4 + 1][r] = v.y;
                As[ac4 + 2][r] = v.z;
                As[ac4 + 3][r] = v.w;
            }
        }
        // ---- load B tile (W rows o0..o0+127, k0..k0+15) ----
        {
            int orow = tid >> 2;
            int kc4  = (tid & 3) * 4;
#pragma unroll
            for (int rr = 0; rr < 2; rr++) {
                int r = orow + rr * 64;
                float4 w = *(const float4*)&W[(size_t)(o0 + r) * Kin + k0 + kc4];
                Bs[kc4 + 0][r] = w.x;
                Bs[kc4 + 1][r] = w.y;
                Bs[kc4 + 2][r] = w.z;
                Bs[kc4 + 3][r] = w.w;
            }
        }
        __syncthreads();
#pragma unroll
        for (int k = 0; k < 16; k++) {
            float a[8], b[8];
            *(float4*)&a[0] = *(const float4*)&As[k][ty * 8];
            *(float4*)&a[4] = *(const float4*)&As[k][ty * 8 + 4];
            *(float4*)&b[0] = *(const float4*)&Bs[k][tx * 8];
            *(float4*)&b[4] = *(const float4*)&Bs[k][tx * 8 + 4];
#pragma unroll
            for (int ii = 0; ii < 8; ii++)
#pragma unroll
                for (int jj = 0; jj < 8; jj++) acc[ii][jj] += a[ii] * b[jj];
        }
        __syncthreads();
    }

    // epilogue: y = relu(acc * s[o] + (b[o]*s[o] + t[o]))
    float al[8], be[8];
#pragma unroll
    for (int jj = 0; jj < 8; jj++) {
        int o = o0 + tx * 8 + jj;
        float sv = sc[o];
        al[jj] = sv;
        be[jj] = bias[o] * sv + sh[o];
    }

    if (!STORE_T) {
#pragma unroll
        for (int ii = 0; ii < 8; ii++) {
            int m = m0 + ty * 8 + ii;
            float4 v0, v1;
            v0.x = relu_(acc[ii][0] * al[0] + be[0]);
            v0.y = relu_(acc[ii][1] * al[1] + be[1]);
            v0.z = relu_(acc[ii][2] * al[2] + be[2]);
            v0.w = relu_(acc[ii][3] * al[3] + be[3]);
            v1.x = relu_(acc[ii][4] * al[4] + be[4]);
            v1.y = relu_(acc[ii][5] * al[5] + be[5]);
            v1.z = relu_(acc[ii][6] * al[6] + be[6]);
            v1.w = relu_(acc[ii][7] * al[7] + be[7]);
            *(float4*)&out[(size_t)m * Nout + o0 + tx * 8]     = v0;
            *(float4*)&out[(size_t)m * Nout + o0 + tx * 8 + 4] = v1;
        }
    } else {
#pragma unroll
        for (int jj = 0; jj < 8; jj++) {
            int o = o0 + tx * 8 + jj;
            float* ob = out + ((size_t)n * Nout + o) * HWSZ + s0 + ty * 8;
#pragma unroll
            for (int ii = 0; ii < 8; ii++)
                ob[ii] = relu_(acc[ii][jj] * al[jj] + be[jj]);
        }
    }
}

// ---------------------------------------------------------------------------
extern "C" void kernel_launch(void* const* d_in, const int* in_sizes, int n_in,
                              void* d_out, int out_size)
{
    const float* feats = (const float*)d_in[0];
    const float* probs = (const float*)d_in[1];
    const float* wp1 = (const float*)d_in[2];
    const float* bp1 = (const float*)d_in[3];
    const float* sp1 = (const float*)d_in[4];
    const float* tp1 = (const float*)d_in[5];
    const float* wp2 = (const float*)d_in[6];
    const float* bp2 = (const float*)d_in[7];
    const float* sp2 = (const float*)d_in[8];
    const float* tp2 = (const float*)d_in[9];
    const float* wo1 = (const float*)d_in[10];
    const float* bo1 = (const float*)d_in[11];
    const float* so1 = (const float*)d_in[12];
    const float* to1 = (const float*)d_in[13];
    const float* wo2 = (const float*)d_in[14];
    const float* bo2 = (const float*)d_in[15];
    const float* so2 = (const float*)d_in[16];
    const float* to2 = (const float*)d_in[17];
    const float* wd  = (const float*)d_in[18];
    const float* bd  = (const float*)d_in[19];
    const float* sd  = (const float*)d_in[20];
    const float* td  = (const float*)d_in[21];
    const float* wu  = (const float*)d_in[22];
    const float* bu  = (const float*)d_in[23];
    const float* su  = (const float*)d_in[24];
    const float* tu  = (const float*)d_in[25];
    const float* wf  = (const float*)d_in[26];
    const float* bf  = (const float*)d_in[27];
    const float* sf  = (const float*)d_in[28];
    const float* tf  = (const float*)d_in[29];
    // d_in[30] = clip_num (unused; always 0)

    float *p, *proxy, *kk, *val, *buf1, *q, *u;
    cudaGetSymbolAddress((void**)&p,     g_p);
    cudaGetSymbolAddress((void**)&proxy, g_proxy);
    cudaGetSymbolAddress((void**)&kk,    g_kk);
    cudaGetSymbolAddress((void**)&val,   g_val);
    cudaGetSymbolAddress((void**)&buf1,  g_buf1);
    cudaGetSymbolAddress((void**)&q,     g_q);
    cudaGetSymbolAddress((void**)&u,     g_u);

    float* out = (float*)d_out;

    // 1) softmax over spatial
    softmax_p_kernel<<<NB * KCLS, 256>>>(probs, p);
    // 2) class-weighted pooling -> proxy
    proxy_kernel<<<NB * (CIN / 4), 256>>>(feats, p, proxy);
    // 3) object branch -> kk, val
    obj_kernel<<<NB * KCLS, 256>>>(proxy,
                                   wo1, bo1, so1, to1,
                                   wo2, bo2, so2, to2,
                                   wd, bd, sd, td,
                                   kk, val);
    // 4) f_pixel stage 1: feats (channel-major) -> q1 (row-major)
    gemm_cbr<1, false><<<dim3(MTOT / 128, KC / 128), 256>>>(
        feats, nullptr, wp1, bp1, sp1, tp1, buf1, KC, CIN, 0, 0, CIN);
    // 5) f_pixel stage 2: q1 -> q
    gemm_cbr<0, false><<<dim3(MTOT / 128, KC / 128), 256>>>(
        buf1, nullptr, wp2, bp2, sp2, tp2, q, KC, KC, 0, KC, 0);
    // 6) attention: q, kk, val -> ctx (reuse buf1)
    attn_kernel<<<MTOT / 64, 256>>>(q, kk, val, buf1);
    // 7) f_up: ctx -> u
    gemm_cbr<0, false><<<dim3(MTOT / 128, CIN / 128), 256>>>(
        buf1, nullptr, wu, bu, su, tu, u, CIN, KC, 0, KC, 0);
    // 8) final fusion: cat(u, feats) -> out (channel-major store)
    gemm_cbr<2, true><<<dim3(MTOT / 128, OUTC / 128), 256>>>(
        u, feats, wf, bf, sf, tf, out, OUTC, 2 * CIN, CIN, CIN, CIN);
}

// round 4
// speedup vs baseline: 3.8082x; 3.8082x over previous
#include <cuda_runtime.h>
#include <cuda_bf16.h>
#include <cstdint>

// Problem constants
#define NB    4
#define CIN   512
#define HH    128
#define WW    128
#define HWSZ  16384
#define LOG2HW 14
#define KCLS  19
#define KC    256
#define OUTC  512
#define MTOT  (NB * HWSZ)   // 65536

// Scratch (device globals; no allocations allowed)
static __device__ float g_p[NB * KCLS * HWSZ];          // softmax probs
static __device__ float g_proxy[NB * CIN * KCLS];       // (n, c, k)
static __device__ float g_kk[NB * KC * KCLS];           // (n, kc, k)
static __device__ float g_val[NB * KCLS * KC];          // (n, k, kc)
static __device__ float g_buf1[(size_t)MTOT * KC];      // q1, then ctx   (m, kc)
static __device__ float g_q[(size_t)MTOT * KC];         // q              (m, kc)
static __device__ float g_cat[(size_t)MTOT * 1024];     // [ctx_up | featsT] (m, 1024)

__device__ __forceinline__ float relu_(float x) { return fmaxf(x, 0.0f); }

__device__ __forceinline__ uint32_t f2tf32(float x) {
    uint32_t r;
    asm("cvt.rna.tf32.f32 %0, %1;" : "=r"(r) : "f"(x));
    return r;
}

__device__ __forceinline__ void mma_tf32(float* c, const uint32_t* a,
                                         uint32_t b0, uint32_t b1) {
    asm volatile(
        "mma.sync.aligned.m16n8k8.row.col.f32.tf32.tf32.f32 "
        "{%0,%1,%2,%3}, {%4,%5,%6,%7}, {%8,%9}, {%0,%1,%2,%3};"
        : "+f"(c[0]), "+f"(c[1]), "+f"(c[2]), "+f"(c[3])
        : "r"(a[0]), "r"(a[1]), "r"(a[2]), "r"(a[3]), "r"(b0), "r"(b1));
}

// ---------------------------------------------------------------------------
// tf32 mma.sync GEMM with fused bias/BN/ReLU epilogue.
//   out = relu((A @ W^T + b) * s + t)
// A row-major (M x Kin, leading dim lda). W row-major (Nout x Kin).
// STORE_T false: out row-major with leading dim ld_out.
// STORE_T true : out channel-major (n, o, s).
// CTA tile 128x128, K-chunk 32 (=128B rows), double-buffered smem (64KB dyn).
// 8 warps = 4(m) x 2(n); warp tile 32x64; fragment m16n8k8.
// Smem layout per tile: row r (128B = 32 floats), 16B-chunk j stored at
// chunk (j ^ (r&7)) -> conflict-free STS.128 and LDS.32.
// ---------------------------------------------------------------------------
template<bool STORE_T>
__global__ __launch_bounds__(256, 1)
void gemm_mma(const float* __restrict__ A, const float* __restrict__ W,
              const float* __restrict__ bias, const float* __restrict__ sc,
              const float* __restrict__ sh, float* __restrict__ outp,
              int Nout, int Kin, int lda, int ld_out)
{
    extern __shared__ __align__(16) float smem[];   // 2 * 8192 floats = 64KB

    int tid  = threadIdx.x;
    int wid  = tid >> 5;
    int lane = tid & 31;
    int warp_m = wid & 3;          // 0..3 -> m offset 32*warp_m
    int warp_n = wid >> 2;         // 0..1 -> n offset 64*warp_n
    int t4 = lane >> 2;            // 0..7
    int q  = lane & 3;             // 0..3

    int m0 = blockIdx.x * 128;
    int o0 = blockIdx.y * 128;

    float acc[2][8][4];
#pragma unroll
    for (int mf = 0; mf < 2; mf++)
#pragma unroll
        for (int nf = 0; nf < 8; nf++)
#pragma unroll
            for (int e = 0; e < 4; e++) acc[mf][nf][e] = 0.0f;

    const int nchunk = Kin >> 5;
    float4 ra[4], rb[4];

    // thread -> (row, 16B-chunk) mapping for ldg/sts
    int lrow[4], lj[4];
#pragma unroll
    for (int i = 0; i < 4; i++) {
        int idx = tid + (i << 8);
        lrow[i] = idx >> 3;
        lj[i]   = idx & 7;
    }

    auto ldg = [&](int ic) {
        const float* Ab = A + (size_t)m0 * lda + (ic << 5);
        const float* Bb = W + (size_t)o0 * Kin + (ic << 5);
#pragma unroll
        for (int i = 0; i < 4; i++) {
            ra[i] = *(const float4*)(Ab + (size_t)lrow[i] * lda + (lj[i] << 2));
            rb[i] = *(const float4*)(Bb + (size_t)lrow[i] * Kin + (lj[i] << 2));
        }
    };
    auto sts = [&](int buf) {
        float* sa = smem + (buf << 13);
        float* sb = sa + 4096;
#pragma unroll
        for (int i = 0; i < 4; i++) {
            int r = lrow[i];
            int off = (r << 5) + ((lj[i] ^ (r & 7)) << 2);
            uint4 ua, ub;
            ua.x = f2tf32(ra[i].x); ua.y = f2tf32(ra[i].y);
            ua.z = f2tf32(ra[i].z); ua.w = f2tf32(ra[i].w);
            ub.x = f2tf32(rb[i].x); ub.y = f2tf32(rb[i].y);
            ub.z = f2tf32(rb[i].z); ub.w = f2tf32(rb[i].w);
            *(uint4*)(sa + off) = ua;
            *(uint4*)(sb + off) = ub;
        }
    };
    auto compute = [&](int buf) {
        const float* sa = smem + (buf << 13);
        const float* sb = sa + 4096;
        int r0b = warp_m * 32 + t4;           // a rows base (mf adds 16)
        int rm  = t4;                          // (row&7) for both A rows and B rows
        int rnb = warp_n * 64 + t4;           // b rows base (nf adds 8)
#pragma unroll
        for (int ks = 0; ks < 4; ks++) {
            int c0 = ((2 * ks) ^ rm) << 2;
            int c1 = ((2 * ks + 1) ^ rm) << 2;
            uint32_t a[2][4];
#pragma unroll
            for (int mf = 0; mf < 2; mf++) {
                int r0 = r0b + mf * 16;
                int r1 = r0 + 8;
                a[mf][0] = __float_as_uint(sa[(r0 << 5) + c0 + q]);
                a[mf][1] = __float_as_uint(sa[(r1 << 5) + c0 + q]);
                a[mf][2] = __float_as_uint(sa[(r0 << 5) + c1 + q]);
                a[mf][3] = __float_as_uint(sa[(r1 << 5) + c1 + q]);
            }
#pragma unroll
            for (int nf = 0; nf < 8; nf++) {
                int rn = rnb + nf * 8;
                uint32_t b0 = __float_as_uint(sb[(rn << 5) + c0 + q]);
                uint32_t b1 = __float_as_uint(sb[(rn << 5) + c1 + q]);
                mma_tf32(acc[0][nf], a[0], b0, b1);
                mma_tf32(acc[1][nf], a[1], b0, b1);
            }
        }
    };

    ldg(0);
    sts(0);
    __syncthreads();
    for (int ic = 0; ic < nchunk; ic++) {
        if (ic + 1 < nchunk) ldg(ic + 1);
        compute(ic & 1);
        if (ic + 1 < nchunk) sts((ic + 1) & 1);
        __syncthreads();
    }

    // Epilogue
    int ob = o0 + warp_n * 64;
    float al[16], be[16];
#pragma unroll
    for (int nf = 0; nf < 8; nf++)
#pragma unroll
        for (int e = 0; e < 2; e++) {
            int o = ob + nf * 8 + 2 * q + e;
            float sv = sc[o];
            al[nf * 2 + e] = sv;
            be[nf * 2 + e] = bias[o] * sv + sh[o];
        }

    if (!STORE_T) {
#pragma unroll
        for (int mf = 0; mf < 2; mf++)
#pragma unroll
            for (int h = 0; h < 2; h++) {
                int m = m0 + warp_m * 32 + mf * 16 + t4 + h * 8;
                float* orow = outp + (size_t)m * ld_out;
#pragma unroll
                for (int nf = 0; nf < 8; nf++) {
                    int n = ob + nf * 8 + 2 * q;
                    float2 v;
                    v.x = relu_(acc[mf][nf][h * 2 + 0] * al[nf * 2 + 0] + be[nf * 2 + 0]);
                    v.y = relu_(acc[mf][nf][h * 2 + 1] * al[nf * 2 + 1] + be[nf * 2 + 1]);
                    *(float2*)(orow + n) = v;
                }
            }
    } else {
#pragma unroll
        for (int mf = 0; mf < 2; mf++)
#pragma unroll
            for (int h = 0; h < 2; h++) {
                int m = m0 + warp_m * 32 + mf * 16 + t4 + h * 8;
                int nb = m >> LOG2HW;
                int s  = m & (HWSZ - 1);
                float* obase = outp + (size_t)nb * Nout * HWSZ + s;
#pragma unroll
                for (int nf = 0; nf < 8; nf++) {
                    int o = ob + nf * 8 + 2 * q;
                    obase[(size_t)o * HWSZ] =
                        relu_(acc[mf][nf][h * 2 + 0] * al[nf * 2 + 0] + be[nf * 2 + 0]);
                    obase[(size_t)(o + 1) * HWSZ] =
                        relu_(acc[mf][nf][h * 2 + 1] * al[nf * 2 + 1] + be[nf * 2 + 1]);
                }
            }
    }
}

// ---------------------------------------------------------------------------
// Transpose feats (n,c,s) into the right half of g_cat: cat[m, 512+c].
// ---------------------------------------------------------------------------
__global__ __launch_bounds__(256)
void transpose_feats(const float* __restrict__ feats, float* __restrict__ cat)
{
    __shared__ float t[32][33];
    int sb = blockIdx.x * 32;
    int cb = blockIdx.y * 32;
    int n  = blockIdx.z;
    int tx = threadIdx.x & 31, ty = threadIdx.x >> 5;   // ty 0..7
    const float* fb = feats + ((size_t)n * CIN + cb) * HWSZ + sb;
#pragma unroll
    for (int j = 0; j < 4; j++)
        t[ty + j * 8][tx] = fb[(size_t)(ty + j * 8) * HWSZ + tx];
    __syncthreads();
    float* ob = cat + ((size_t)(n * HWSZ + sb)) * 1024 + 512 + cb;
#pragma unroll
    for (int j = 0; j < 4; j++)
        ob[(size_t)(ty + j * 8) * 1024 + tx] = t[tx][ty + j * 8];
}

// ---------------------------------------------------------------------------
// softmax of probs over spatial dim. One block per (n,k) row.
// ---------------------------------------------------------------------------
__global__ __launch_bounds__(256)
void softmax_p_kernel(const float* __restrict__ probs, float* __restrict__ p)
{
    int row = blockIdx.x;
    const float* src = probs + (size_t)row * HWSZ;
    float*       dst = p     + (size_t)row * HWSZ;
    int tid = threadIdx.x;
    __shared__ float red[256];

    float m = -1e30f;
    for (int i = tid; i < HWSZ; i += 256) m = fmaxf(m, src[i]);
    red[tid] = m; __syncthreads();
    for (int s = 128; s > 0; s >>= 1) {
        if (tid < s) red[tid] = fmaxf(red[tid], red[tid + s]);
        __syncthreads();
    }
    m = red[0]; __syncthreads();

    float sum = 0.0f;
    for (int i = tid; i < HWSZ; i += 256) sum += __expf(src[i] - m);
    red[tid] = sum; __syncthreads();
    for (int s = 128; s > 0; s >>= 1) {
        if (tid < s) red[tid] += red[tid + s];
        __syncthreads();
    }
    float inv = 1.0f / red[0];

    for (int i = tid; i < HWSZ; i += 256) dst[i] = __expf(src[i] - m) * inv;
}

// ---------------------------------------------------------------------------
// proxy[n,c,k] = sum_s p[n,k,s] * feats[n,c,s].
// ---------------------------------------------------------------------------
__global__ __launch_bounds__(256)
void proxy_kernel(const float* __restrict__ feats, const float* __restrict__ p,
                  float* __restrict__ proxy)
{
    int b  = blockIdx.x;
    int n  = b / (CIN / 4);
    int c0 = (b % (CIN / 4)) * 4;
    int tid = threadIdx.x;

    float acc[4][KCLS];
#pragma unroll
    for (int cc = 0; cc < 4; cc++)
#pragma unroll
        for (int k = 0; k < KCLS; k++) acc[cc][k] = 0.0f;

    const float* pb = p     + (size_t)n * KCLS * HWSZ;
    const float* fb = feats + ((size_t)n * CIN + c0) * HWSZ;

    for (int s = tid; s < HWSZ; s += 256) {
        float pv[KCLS];
#pragma unroll
        for (int k = 0; k < KCLS; k++) pv[k] = pb[k * HWSZ + s];
#pragma unroll
        for (int cc = 0; cc < 4; cc++) {
            float f = fb[cc * HWSZ + s];
#pragma unroll
            for (int k = 0; k < KCLS; k++) acc[cc][k] += f * pv[k];
        }
    }

    __shared__ float red[8][80];
    int lane = tid & 31, wp = tid >> 5;
#pragma unroll
    for (int cc = 0; cc < 4; cc++)
#pragma unroll
        for (int k = 0; k < KCLS; k++) {
            float v = acc[cc][k];
            v += __shfl_down_sync(0xffffffffu, v, 16);
            v += __shfl_down_sync(0xffffffffu, v, 8);
            v += __shfl_down_sync(0xffffffffu, v, 4);
            v += __shfl_down_sync(0xffffffffu, v, 2);
            v += __shfl_down_sync(0xffffffffu, v, 1);
            if (lane == 0) red[wp][cc * KCLS + k] = v;
        }
    __syncthreads();
    if (tid < 4 * KCLS) {
        float s2 = 0.0f;
#pragma unroll
        for (int w2 = 0; w2 < 8; w2++) s2 += red[w2][tid];
        int cc = tid / KCLS, k = tid % KCLS;
        proxy[((size_t)n * CIN + c0 + cc) * KCLS + k] = s2;
    }
}

// ---------------------------------------------------------------------------
// Object branch: kk, val from proxy. One block per (n,k).
// ---------------------------------------------------------------------------
__global__ __launch_bounds__(256)
void obj_kernel(const float* __restrict__ proxy,
                const float* __restrict__ wo1, const float* __restrict__ bo1,
                const float* __restrict__ so1, const float* __restrict__ to1,
                const float* __restrict__ wo2, const float* __restrict__ bo2,
                const float* __restrict__ so2, const float* __restrict__ to2,
                const float* __restrict__ wd,  const float* __restrict__ bd,
                const float* __restrict__ sd,  const float* __restrict__ td,
                float* __restrict__ kkout, float* __restrict__ valout)
{
    int n = blockIdx.x / KCLS, k = blockIdx.x % KCLS;
    int tid = threadIdx.x;
    __shared__ float col[CIN];
    __shared__ float h1[KC];

    const float* pc = proxy + (size_t)n * CIN * KCLS + k;
    col[tid]       = pc[(size_t)tid * KCLS];
    col[tid + 256] = pc[(size_t)(tid + 256) * KCLS];
    __syncthreads();

    float a1 = 0.0f, av = 0.0f;
    const float* w1 = wo1 + (size_t)tid * CIN;
    const float* wv = wd  + (size_t)tid * CIN;
#pragma unroll 4
    for (int c = 0; c < CIN; c++) {
        float x = col[c];
        a1 += x * w1[c];
        av += x * wv[c];
    }
    a1 = relu_((a1 + bo1[tid]) * so1[tid] + to1[tid]);
    av = relu_((av + bd[tid])  * sd[tid]  + td[tid]);
    valout[((size_t)n * KCLS + k) * KC + tid] = av;
    h1[tid] = a1;
    __syncthreads();

    float a2 = 0.0f;
    const float* w2 = wo2 + (size_t)tid * KC;
#pragma unroll 4
    for (int c = 0; c < KC; c++) a2 += h1[c] * w2[c];
    a2 = relu_((a2 + bo2[tid]) * so2[tid] + to2[tid]);
    kkout[((size_t)n * KC + tid) * KCLS + k] = a2;
}

// ---------------------------------------------------------------------------
// Attention: logits(64x19) -> softmax -> ctx(64x256). One block = 64 pixels.
// ---------------------------------------------------------------------------
__global__ __launch_bounds__(256)
void attn_kernel(const float* __restrict__ q, const float* __restrict__ kk,
                 const float* __restrict__ val, float* __restrict__ ctx)
{
    int m0 = blockIdx.x * 64;
    int n  = m0 >> LOG2HW;
    int tid = threadIdx.x;

    __shared__ float kks[KC][KCLS];
    __shared__ float qs[64][33];
    __shared__ float sims[64][20];

    const float* kkb = kk + (size_t)n * KC * KCLS;
    for (int i = tid; i < KC * KCLS; i += 256) {
        kks[i / KCLS][i % KCLS] = kkb[i];
    }
    __syncthreads();

    int i = tid & 63;
    int g = tid >> 6;
    float acc[5];
#pragma unroll
    for (int z = 0; z < 5; z++) acc[z] = 0.0f;

    for (int kc0 = 0; kc0 < KC; kc0 += 32) {
        int r  = tid >> 3;
        int c4 = (tid & 7) * 4;
#pragma unroll
        for (int rr = 0; rr < 2; rr++) {
            float4 v = *(const float4*)&q[(size_t)(m0 + r + rr * 32) * KC + kc0 + c4];
            qs[r + rr * 32][c4 + 0] = v.x;
            qs[r + rr * 32][c4 + 1] = v.y;
            qs[r + rr * 32][c4 + 2] = v.z;
            qs[r + rr * 32][c4 + 3] = v.w;
        }
        __syncthreads();
#pragma unroll 8
        for (int kc = 0; kc < 32; kc++) {
            float a = qs[i][kc];
#pragma unroll
            for (int z = 0; z < 5; z++) {
                int k = g + z * 4;
                if (k < KCLS) acc[z] += a * kks[kc0 + kc][k];
            }
        }
        __syncthreads();
    }

#pragma unroll
    for (int z = 0; z < 5; z++) {
        int k = g + z * 4;
        if (k < KCLS) sims[i][k] = acc[z] * 0.0625f;
    }
    __syncthreads();

    if (tid < 64) {
        float m = -1e30f;
#pragma unroll
        for (int k = 0; k < KCLS; k++) m = fmaxf(m, sims[tid][k]);
        float s = 0.0f;
        float e[KCLS];
#pragma unroll
        for (int k = 0; k < KCLS; k++) { e[k] = __expf(sims[tid][k] - m); s += e[k]; }
        float inv = 1.0f / s;
#pragma unroll
        for (int k = 0; k < KCLS; k++) sims[tid][k] = e[k] * inv;
    }
    __syncthreads();

    float vreg[KCLS];
    const float* vb = val + (size_t)n * KCLS * KC + tid;
#pragma unroll
    for (int k = 0; k < KCLS; k++) vreg[k] = vb[k * KC];

    for (int ii = 0; ii < 64; ii++) {
        float a = 0.0f;
#pragma unroll
        for (int k = 0; k < KCLS; k++) a += sims[ii][k] * vreg[k];
        ctx[(size_t)(m0 + ii) * KC + tid] = a;
    }
}

// ---------------------------------------------------------------------------
extern "C" void kernel_launch(void* const* d_in, const int* in_sizes, int n_in,
                              void* d_out, int out_size)
{
    const float* feats = (const float*)d_in[0];
    const float* probs = (const float*)d_in[1];
    const float* wp1 = (const float*)d_in[2];
    const float* bp1 = (const float*)d_in[3];
    const float* sp1 = (const float*)d_in[4];
    const float* tp1 = (const float*)d_in[5];
    const float* wp2 = (const float*)d_in[6];
    const float* bp2 = (const float*)d_in[7];
    const float* sp2 = (const float*)d_in[8];
    const float* tp2 = (const float*)d_in[9];
    const float* wo1 = (const float*)d_in[10];
    const float* bo1 = (const float*)d_in[11];
    const float* so1 = (const float*)d_in[12];
    const float* to1 = (const float*)d_in[13];
    const float* wo2 = (const float*)d_in[14];
    const float* bo2 = (const float*)d_in[15];
    const float* so2 = (const float*)d_in[16];
    const float* to2 = (const float*)d_in[17];
    const float* wd  = (const float*)d_in[18];
    const float* bd  = (const float*)d_in[19];
    const float* sd  = (const float*)d_in[20];
    const float* td  = (const float*)d_in[21];
    const float* wu  = (const float*)d_in[22];
    const float* bu  = (const float*)d_in[23];
    const float* su  = (const float*)d_in[24];
    const float* tu  = (const float*)d_in[25];
    const float* wf  = (const float*)d_in[26];
    const float* bf  = (const float*)d_in[27];
    const float* sf  = (const float*)d_in[28];
    const float* tf  = (const float*)d_in[29];

    float *p, *proxy, *kk, *val, *buf1, *q, *cat;
    cudaGetSymbolAddress((void**)&p,     g_p);
    cudaGetSymbolAddress((void**)&proxy, g_proxy);
    cudaGetSymbolAddress((void**)&kk,    g_kk);
    cudaGetSymbolAddress((void**)&val,   g_val);
    cudaGetSymbolAddress((void**)&buf1,  g_buf1);
    cudaGetSymbolAddress((void**)&q,     g_q);
    cudaGetSymbolAddress((void**)&cat,   g_cat);

    float* out = (float*)d_out;

    const int SMEM_DYN = 2 * 8192 * 4;   // 64KB: double-buffered A+B tiles
    cudaFuncSetAttribute(gemm_mma<false>, cudaFuncAttributeMaxDynamicSharedMemorySize, SMEM_DYN);
    cudaFuncSetAttribute(gemm_mma<true>,  cudaFuncAttributeMaxDynamicSharedMemorySize, SMEM_DYN);

    // 0) transpose feats into right half of concat buffer
    transpose_feats<<<dim3(HWSZ / 32, CIN / 32, NB), 256>>>(feats, cat);
    // 1) softmax over spatial
    softmax_p_kernel<<<NB * KCLS, 256>>>(probs, p);
    // 2) class-weighted pooling -> proxy
    proxy_kernel<<<NB * (CIN / 4), 256>>>(feats, p, proxy);
    // 3) object branch -> kk, val
    obj_kernel<<<NB * KCLS, 256>>>(proxy,
                                   wo1, bo1, so1, to1,
                                   wo2, bo2, so2, to2,
                                   wd, bd, sd, td,
                                   kk, val);
    // 4) f_pixel stage 1: featsT -> q1
    gemm_mma<false><<<dim3(MTOT / 128, KC / 128), 256, SMEM_DYN>>>(
        cat + 512, wp1, bp1, sp1, tp1, buf1, KC, CIN, 1024, KC);
    // 5) f_pixel stage 2: q1 -> q
    gemm_mma<false><<<dim3(MTOT / 128, KC / 128), 256, SMEM_DYN>>>(
        buf1, wp2, bp2, sp2, tp2, q, KC, KC, KC, KC);
    // 6) attention: q, kk, val -> ctx (reuse buf1)
    attn_kernel<<<MTOT / 64, 256>>>(q, kk, val, buf1);
    // 7) f_up: ctx -> left half of concat buffer
    gemm_mma<false><<<dim3(MTOT / 128, CIN / 128), 256, SMEM_DYN>>>(
        buf1, wu, bu, su, tu, cat, CIN, KC, KC, 1024);
    // 8) final fusion: cat -> out (channel-major store)
    gemm_mma<true><<<dim3(MTOT / 128, OUTC / 128), 256, SMEM_DYN>>>(
        cat, wf, bf, sf, tf, out, OUTC, 2 * CIN, 1024, 0);
}

// round 5
// speedup vs baseline: 4.0992x; 1.0764x over previous
#include <cuda_runtime.h>
#include <cuda_bf16.h>
#include <cstdint>

// Problem constants
#define NB    4
#define CIN   512
#define HH    128
#define WW    128
#define HWSZ  16384
#define LOG2HW 14
#define KCLS  19
#define KC    256
#define OUTC  512
#define MTOT  (NB * HWSZ)   // 65536

// Scratch (device globals; no allocations allowed)
static __device__ float g_p[NB * KCLS * HWSZ];          // softmax probs
static __device__ float g_proxy[NB * CIN * KCLS];       // (n, c, k)
static __device__ float g_kk[NB * KC * KCLS];           // (n, kc, k)
static __device__ float g_val[NB * KCLS * KC];          // (n, k, kc)
static __device__ float g_buf1[(size_t)MTOT * KC];      // q1, then ctx   (m, kc)
static __device__ float g_q[(size_t)MTOT * KC];         // q              (m, kc)
static __device__ float g_cat[(size_t)MTOT * 1024];     // [ctx_up | featsT] (m, 1024)
static __device__ float g_wo1t[CIN * KC];               // wo1^T (c, o)
static __device__ float g_wdt[CIN * KC];                // wd^T  (c, o)
static __device__ float g_wo2t[KC * KC];                // wo2^T (c, o)

__device__ __forceinline__ float relu_(float x) { return fmaxf(x, 0.0f); }

__device__ __forceinline__ uint32_t f2tf32(float x) {
    uint32_t r;
    asm("cvt.rna.tf32.f32 %0, %1;" : "=r"(r) : "f"(x));
    return r;
}

__device__ __forceinline__ void mma_tf32(float* c, const uint32_t* a,
                                         uint32_t b0, uint32_t b1) {
    asm volatile(
        "mma.sync.aligned.m16n8k8.row.col.f32.tf32.tf32.f32 "
        "{%0,%1,%2,%3}, {%4,%5,%6,%7}, {%8,%9}, {%0,%1,%2,%3};"
        : "+f"(c[0]), "+f"(c[1]), "+f"(c[2]), "+f"(c[3])
        : "r"(a[0]), "r"(a[1]), "r"(a[2]), "r"(a[3]), "r"(b0), "r"(b1));
}

// ---------------------------------------------------------------------------
// tf32 mma.sync GEMM with fused bias/BN/ReLU epilogue.
//   out = relu((A @ W^T + b) * s + t)
// A row-major (M x KIN, leading dim lda). W row-major (Nout x KIN).
// Grid: (Nout/128, MTOT/128) -- o-tile fastest so co-resident CTAs share the
// A tile through L2 (A DRAM traffic read once per wave, not once per o-tile).
// STORE_T false: out row-major with leading dim ld_out.
// STORE_T true : out channel-major (n, o, s).
// CTA tile 128x128, K-chunk 32 (=128B rows), double-buffered smem (64KB dyn).
// 8 warps = 4(m) x 2(n); warp tile 32x64; fragment m16n8k8.
// Smem: row r (32 floats), 16B-chunk j stored at chunk (j ^ (r&7)).
// ---------------------------------------------------------------------------
template<bool STORE_T, int KIN>
__global__ __launch_bounds__(256, 1)
void gemm_mma(const float* __restrict__ A, const float* __restrict__ W,
              const float* __restrict__ bias, const float* __restrict__ sc,
              const float* __restrict__ sh, float* __restrict__ outp,
              int Nout, int lda, int ld_out)
{
    extern __shared__ __align__(16) float smem[];   // 2 * 8192 floats = 64KB

    int tid  = threadIdx.x;
    int wid  = tid >> 5;
    int lane = tid & 31;
    int warp_m = wid & 3;          // 0..3 -> m offset 32*warp_m
    int warp_n = wid >> 2;         // 0..1 -> n offset 64*warp_n
    int t4 = lane >> 2;            // 0..7
    int q  = lane & 3;             // 0..3

    int o0 = blockIdx.x * 128;
    int m0 = blockIdx.y * 128;

    float acc[2][8][4];
#pragma unroll
    for (int mf = 0; mf < 2; mf++)
#pragma unroll
        for (int nf = 0; nf < 8; nf++)
#pragma unroll
            for (int e = 0; e < 4; e++) acc[mf][nf][e] = 0.0f;

    constexpr int nchunk = KIN >> 5;
    float4 ra[4], rb[4];

    // thread -> (row, 16B-chunk) mapping for ldg/sts
    int lrow[4], lj[4];
#pragma unroll
    for (int i = 0; i < 4; i++) {
        int idx = tid + (i << 8);
        lrow[i] = idx >> 3;
        lj[i]   = idx & 7;
    }

    auto ldg = [&](int ic) {
        const float* Ab = A + (size_t)m0 * lda + (ic << 5);
        const float* Bb = W + (size_t)o0 * KIN + (ic << 5);
#pragma unroll
        for (int i = 0; i < 4; i++) {
            ra[i] = *(const float4*)(Ab + (size_t)lrow[i] * lda + (lj[i] << 2));
            rb[i] = *(const float4*)(Bb + (size_t)lrow[i] * KIN + (lj[i] << 2));
        }
    };
    auto sts = [&](int buf) {
        float* sa = smem + (buf << 13);
        float* sb = sa + 4096;
#pragma unroll
        for (int i = 0; i < 4; i++) {
            int r = lrow[i];
            int off = (r << 5) + ((lj[i] ^ (r & 7)) << 2);
            uint4 ua, ub;
            ua.x = f2tf32(ra[i].x); ua.y = f2tf32(ra[i].y);
            ua.z = f2tf32(ra[i].z); ua.w = f2tf32(ra[i].w);
            ub.x = f2tf32(rb[i].x); ub.y = f2tf32(rb[i].y);
            ub.z = f2tf32(rb[i].z); ub.w = f2tf32(rb[i].w);
            *(uint4*)(sa + off) = ua;
            *(uint4*)(sb + off) = ub;
        }
    };
    auto compute = [&](int buf) {
        const float* sa = smem + (buf << 13);
        const float* sb = sa + 4096;
        int r0b = warp_m * 32 + t4;           // a rows base (mf adds 16)
        int rm  = t4;                          // (row&7)
        int rnb = warp_n * 64 + t4;           // b rows base (nf adds 8)
#pragma unroll
        for (int ks = 0; ks < 4; ks++) {
            int c0 = ((2 * ks) ^ rm) << 2;
            int c1 = ((2 * ks + 1) ^ rm) << 2;
            uint32_t a[2][4];
#pragma unroll
            for (int mf = 0; mf < 2; mf++) {
                int r0 = r0b + mf * 16;
                int r1 = r0 + 8;
                a[mf][0] = __float_as_uint(sa[(r0 << 5) + c0 + q]);
                a[mf][1] = __float_as_uint(sa[(r1 << 5) + c0 + q]);
                a[mf][2] = __float_as_uint(sa[(r0 << 5) + c1 + q]);
                a[mf][3] = __float_as_uint(sa[(r1 << 5) + c1 + q]);
            }
#pragma unroll
            for (int nf = 0; nf < 8; nf++) {
                int rn = rnb + nf * 8;
                uint32_t b0 = __float_as_uint(sb[(rn << 5) + c0 + q]);
                uint32_t b1 = __float_as_uint(sb[(rn << 5) + c1 + q]);
                mma_tf32(acc[0][nf], a[0], b0, b1);
                mma_tf32(acc[1][nf], a[1], b0, b1);
            }
        }
    };

    ldg(0);
    sts(0);
    __syncthreads();
#pragma unroll 2
    for (int ic = 0; ic < nchunk; ic++) {
        if (ic + 1 < nchunk) ldg(ic + 1);
        compute(ic & 1);
        if (ic + 1 < nchunk) sts((ic + 1) & 1);
        __syncthreads();
    }

    // Epilogue
    int ob = o0 + warp_n * 64;
    float al[16], be[16];
#pragma unroll
    for (int nf = 0; nf < 8; nf++)
#pragma unroll
        for (int e = 0; e < 2; e++) {
            int o = ob + nf * 8 + 2 * q + e;
            float sv = sc[o];
            al[nf * 2 + e] = sv;
            be[nf * 2 + e] = bias[o] * sv + sh[o];
        }

    if (!STORE_T) {
#pragma unroll
        for (int mf = 0; mf < 2; mf++)
#pragma unroll
            for (int h = 0; h < 2; h++) {
                int m = m0 + warp_m * 32 + mf * 16 + t4 + h * 8;
                float* orow = outp + (size_t)m * ld_out;
#pragma unroll
                for (int nf = 0; nf < 8; nf++) {
                    int n = ob + nf * 8 + 2 * q;
                    float2 v;
                    v.x = relu_(acc[mf][nf][h * 2 + 0] * al[nf * 2 + 0] + be[nf * 2 + 0]);
                    v.y = relu_(acc[mf][nf][h * 2 + 1] * al[nf * 2 + 1] + be[nf * 2 + 1]);
                    *(float2*)(orow + n) = v;
                }
            }
    } else {
#pragma unroll
        for (int mf = 0; mf < 2; mf++)
#pragma unroll
            for (int h = 0; h < 2; h++) {
                int m = m0 + warp_m * 32 + mf * 16 + t4 + h * 8;
                int nb = m >> LOG2HW;
                int s  = m & (HWSZ - 1);
                float* obase = outp + (size_t)nb * Nout * HWSZ + s;
#pragma unroll
                for (int nf = 0; nf < 8; nf++) {
                    int o = ob + nf * 8 + 2 * q;
                    obase[(size_t)o * HWSZ] =
                        relu_(acc[mf][nf][h * 2 + 0] * al[nf * 2 + 0] + be[nf * 2 + 0]);
                    obase[(size_t)(o + 1) * HWSZ] =
                        relu_(acc[mf][nf][h * 2 + 1] * al[nf * 2 + 1] + be[nf * 2 + 1]);
                }
            }
    }
}

// ---------------------------------------------------------------------------
// Transpose feats (n,c,s) into the right half of g_cat: cat[m, 512+c].
// ---------------------------------------------------------------------------
__global__ __launch_bounds__(256)
void transpose_feats(const float* __restrict__ feats, float* __restrict__ cat)
{
    __shared__ float t[32][33];
    int sb = blockIdx.x * 32;
    int cb = blockIdx.y * 32;
    int n  = blockIdx.z;
    int tx = threadIdx.x & 31, ty = threadIdx.x >> 5;   // ty 0..7
    const float* fb = feats + ((size_t)n * CIN + cb) * HWSZ + sb;
#pragma unroll
    for (int j = 0; j < 4; j++)
        t[ty + j * 8][tx] = fb[(size_t)(ty + j * 8) * HWSZ + tx];
    __syncthreads();
    float* ob = cat + ((size_t)(n * HWSZ + sb)) * 1024 + 512 + cb;
#pragma unroll
    for (int j = 0; j < 4; j++)
        ob[(size_t)(ty + j * 8) * 1024 + tx] = t[tx][ty + j * 8];
}

// ---------------------------------------------------------------------------
// Generic small weight transpose: out[c * O + o] = in[o * C + c].
// Grid: (C/32, O/32). 256 threads.
// ---------------------------------------------------------------------------
__global__ __launch_bounds__(256)
void wtrans_kernel(const float* __restrict__ in, float* __restrict__ out,
                   int O, int C)
{
    __shared__ float t[32][33];
    int cb = blockIdx.x * 32;
    int ob = blockIdx.y * 32;
    int tx = threadIdx.x & 31, ty = threadIdx.x >> 5;
#pragma unroll
    for (int j = 0; j < 4; j++)
        t[ty + j * 8][tx] = in[(size_t)(ob + ty + j * 8) * C + cb + tx];
    __syncthreads();
#pragma unroll
    for (int j = 0; j < 4; j++)
        out[(size_t)(cb + ty + j * 8) * O + ob + tx] = t[tx][ty + j * 8];
}

// ---------------------------------------------------------------------------
// softmax of probs over spatial dim. One block per (n,k) row.
// ---------------------------------------------------------------------------
__global__ __launch_bounds__(256)
void softmax_p_kernel(const float* __restrict__ probs, float* __restrict__ p)
{
    int row = blockIdx.x;
    const float* src = probs + (size_t)row * HWSZ;
    float*       dst = p     + (size_t)row * HWSZ;
    int tid = threadIdx.x;
    __shared__ float red[256];

    float m = -1e30f;
    for (int i = tid; i < HWSZ; i += 256) m = fmaxf(m, src[i]);
    red[tid] = m; __syncthreads();
    for (int s = 128; s > 0; s >>= 1) {
        if (tid < s) red[tid] = fmaxf(red[tid], red[tid + s]);
        __syncthreads();
    }
    m = red[0]; __syncthreads();

    float sum = 0.0f;
    for (int i = tid; i < HWSZ; i += 256) sum += __expf(src[i] - m);
    red[tid] = sum; __syncthreads();
    for (int s = 128; s > 0; s >>= 1) {
        if (tid < s) red[tid] += red[tid + s];
        __syncthreads();
    }
    float inv = 1.0f / red[0];

    for (int i = tid; i < HWSZ; i += 256) dst[i] = __expf(src[i] - m) * inv;
}

// ---------------------------------------------------------------------------
// proxy[n,c,k] = sum_s p[n,k,s] * feats[n,c,s].
// ---------------------------------------------------------------------------
__global__ __launch_bounds__(256)
void proxy_kernel(const float* __restrict__ feats, const float* __restrict__ p,
                  float* __restrict__ proxy)
{
    int b  = blockIdx.x;
    int n  = b / (CIN / 4);
    int c0 = (b % (CIN / 4)) * 4;
    int tid = threadIdx.x;

    float acc[4][KCLS];
#pragma unroll
    for (int cc = 0; cc < 4; cc++)
#pragma unroll
        for (int k = 0; k < KCLS; k++) acc[cc][k] = 0.0f;

    const float* pb = p     + (size_t)n * KCLS * HWSZ;
    const float* fb = feats + ((size_t)n * CIN + c0) * HWSZ;

    for (int s = tid; s < HWSZ; s += 256) {
        float pv[KCLS];
#pragma unroll
        for (int k = 0; k < KCLS; k++) pv[k] = pb[k * HWSZ + s];
#pragma unroll
        for (int cc = 0; cc < 4; cc++) {
            float f = fb[cc * HWSZ + s];
#pragma unroll
            for (int k = 0; k < KCLS; k++) acc[cc][k] += f * pv[k];
        }
    }

    __shared__ float red[8][80];
    int lane = tid & 31, wp = tid >> 5;
#pragma unroll
    for (int cc = 0; cc < 4; cc++)
#pragma unroll
        for (int k = 0; k < KCLS; k++) {
            float v = acc[cc][k];
            v += __shfl_down_sync(0xffffffffu, v, 16);
            v += __shfl_down_sync(0xffffffffu, v, 8);
            v += __shfl_down_sync(0xffffffffu, v, 4);
            v += __shfl_down_sync(0xffffffffu, v, 2);
            v += __shfl_down_sync(0xffffffffu, v, 1);
            if (lane == 0) red[wp][cc * KCLS + k] = v;
        }
    __syncthreads();
    if (tid < 4 * KCLS) {
        float s2 = 0.0f;
#pragma unroll
        for (int w2 = 0; w2 < 8; w2++) s2 += red[w2][tid];
        int cc = tid / KCLS, k = tid % KCLS;
        proxy[((size_t)n * CIN + c0 + cc) * KCLS + k] = s2;
    }
}

// ---------------------------------------------------------------------------
// Object branch with TRANSPOSED weights (coalesced): one block per (n,k).
//   h1 = cbr(col, wo1), kk = cbr(h1, wo2), val = cbr(col, wd)
// ---------------------------------------------------------------------------
__global__ __launch_bounds__(256)
void obj_kernel(const float* __restrict__ proxy,
                const float* __restrict__ wo1t, const float* __restrict__ bo1,
                const float* __restrict__ so1, const float* __restrict__ to1,
                const float* __restrict__ wo2t, const float* __restrict__ bo2,
                const float* __restrict__ so2, const float* __restrict__ to2,
                const float* __restrict__ wdt,  const float* __restrict__ bd,
                const float* __restrict__ sd,  const float* __restrict__ td,
                float* __restrict__ kkout, float* __restrict__ valout)
{
    int n = blockIdx.x / KCLS, k = blockIdx.x % KCLS;
    int tid = threadIdx.x;
    __shared__ float col[CIN];
    __shared__ float h1[KC];

    const float* pc = proxy + (size_t)n * CIN * KCLS + k;
    col[tid]       = pc[(size_t)tid * KCLS];
    col[tid + 256] = pc[(size_t)(tid + 256) * KCLS];
    __syncthreads();

    float a1 = 0.0f, av = 0.0f;
#pragma unroll 8
    for (int c = 0; c < CIN; c++) {
        float x = col[c];
        a1 += x * wo1t[c * KC + tid];
        av += x * wdt[c * KC + tid];
    }
    a1 = relu_((a1 + bo1[tid]) * so1[tid] + to1[tid]);
    av = relu_((av + bd[tid])  * sd[tid]  + td[tid]);
    valout[((size_t)n * KCLS + k) * KC + tid] = av;
    h1[tid] = a1;
    __syncthreads();

    float a2 = 0.0f;
#pragma unroll 8
    for (int c = 0; c < KC; c++) a2 += h1[c] * wo2t[c * KC + tid];
    a2 = relu_((a2 + bo2[tid]) * so2[tid] + to2[tid]);
    kkout[((size_t)n * KC + tid) * KCLS + k] = a2;
}

// ---------------------------------------------------------------------------
// Attention: logits(64x19) -> softmax -> ctx(64x256). One block = 64 pixels.
// ---------------------------------------------------------------------------
__global__ __launch_bounds__(256)
void attn_kernel(const float* __restrict__ q, const float* __restrict__ kk,
                 const float* __restrict__ val, float* __restrict__ ctx)
{
    int m0 = blockIdx.x * 64;
    int n  = m0 >> LOG2HW;
    int tid = threadIdx.x;

    __shared__ float kks[KC][KCLS];
    __shared__ float qs[64][33];
    __shared__ float sims[64][20];

    const float* kkb = kk + (size_t)n * KC * KCLS;
    for (int i = tid; i < KC * KCLS; i += 256) {
        kks[i / KCLS][i % KCLS] = kkb[i];
    }
    __syncthreads();

    int i = tid & 63;
    int g = tid >> 6;
    float acc[5];
#pragma unroll
    for (int z = 0; z < 5; z++) acc[z] = 0.0f;

    for (int kc0 = 0; kc0 < KC; kc0 += 32) {
        int r  = tid >> 3;
        int c4 = (tid & 7) * 4;
#pragma unroll
        for (int rr = 0; rr < 2; rr++) {
            float4 v = *(const float4*)&q[(size_t)(m0 + r + rr * 32) * KC + kc0 + c4];
            qs[r + rr * 32][c4 + 0] = v.x;
            qs[r + rr * 32][c4 + 1] = v.y;
            qs[r + rr * 32][c4 + 2] = v.z;
            qs[r + rr * 32][c4 + 3] = v.w;
        }
        __syncthreads();
#pragma unroll 8
        for (int kc = 0; kc < 32; kc++) {
            float a = qs[i][kc];
#pragma unroll
            for (int z = 0; z < 5; z++) {
                int k = g + z * 4;
                if (k < KCLS) acc[z] += a * kks[kc0 + kc][k];
            }
        }
        __syncthreads();
    }

#pragma unroll
    for (int z = 0; z < 5; z++) {
        int k = g + z * 4;
        if (k < KCLS) sims[i][k] = acc[z] * 0.0625f;
    }
    __syncthreads();

    if (tid < 64) {
        float m = -1e30f;
#pragma unroll
        for (int k = 0; k < KCLS; k++) m = fmaxf(m, sims[tid][k]);
        float s = 0.0f;
        float e[KCLS];
#pragma unroll
        for (int k = 0; k < KCLS; k++) { e[k] = __expf(sims[tid][k] - m); s += e[k]; }
        float inv = 1.0f / s;
#pragma unroll
        for (int k = 0; k < KCLS; k++) sims[tid][k] = e[k] * inv;
    }
    __syncthreads();

    float vreg[KCLS];
    const float* vb = val + (size_t)n * KCLS * KC + tid;
#pragma unroll
    for (int k = 0; k < KCLS; k++) vreg[k] = vb[k * KC];

    for (int ii = 0; ii < 64; ii++) {
        float a = 0.0f;
#pragma unroll
        for (int k = 0; k < KCLS; k++) a += sims[ii][k] * vreg[k];
        ctx[(size_t)(m0 + ii) * KC + tid] = a;
    }
}

// ---------------------------------------------------------------------------
extern "C" void kernel_launch(void* const* d_in, const int* in_sizes, int n_in,
                              void* d_out, int out_size)
{
    const float* feats = (const float*)d_in[0];
    const float* probs = (const float*)d_in[1];
    const float* wp1 = (const float*)d_in[2];
    const float* bp1 = (const float*)d_in[3];
    const float* sp1 = (const float*)d_in[4];
    const float* tp1 = (const float*)d_in[5];
    const float* wp2 = (const float*)d_in[6];
    const float* bp2 = (const float*)d_in[7];
    const float* sp2 = (const float*)d_in[8];
    const float* tp2 = (const float*)d_in[9];
    const float* wo1 = (const float*)d_in[10];
    const float* bo1 = (const float*)d_in[11];
    const float* so1 = (const float*)d_in[12];
    const float* to1 = (const float*)d_in[13];
    const float* wo2 = (const float*)d_in[14];
    const float* bo2 = (const float*)d_in[15];
    const float* so2 = (const float*)d_in[16];
    const float* to2 = (const float*)d_in[17];
    const float* wd  = (const float*)d_in[18];
    const float* bd  = (const float*)d_in[19];
    const float* sd  = (const float*)d_in[20];
    const float* td  = (const float*)d_in[21];
    const float* wu  = (const float*)d_in[22];
    const float* bu  = (const float*)d_in[23];
    const float* su  = (const float*)d_in[24];
    const float* tu  = (const float*)d_in[25];
    const float* wf  = (const float*)d_in[26];
    const float* bf  = (const float*)d_in[27];
    const float* sf  = (const float*)d_in[28];
    const float* tf  = (const float*)d_in[29];

    float *p, *proxy, *kk, *val, *buf1, *q, *cat, *wo1t, *wdt, *wo2t;
    cudaGetSymbolAddress((void**)&p,     g_p);
    cudaGetSymbolAddress((void**)&proxy, g_proxy);
    cudaGetSymbolAddress((void**)&kk,    g_kk);
    cudaGetSymbolAddress((void**)&val,   g_val);
    cudaGetSymbolAddress((void**)&buf1,  g_buf1);
    cudaGetSymbolAddress((void**)&q,     g_q);
    cudaGetSymbolAddress((void**)&cat,   g_cat);
    cudaGetSymbolAddress((void**)&wo1t,  g_wo1t);
    cudaGetSymbolAddress((void**)&wdt,   g_wdt);
    cudaGetSymbolAddress((void**)&wo2t,  g_wo2t);

    float* out = (float*)d_out;

    const int SMEM_DYN = 2 * 8192 * 4;   // 64KB: double-buffered A+B tiles
    cudaFuncSetAttribute(gemm_mma<false, CIN>,     cudaFuncAttributeMaxDynamicSharedMemorySize, SMEM_DYN);
    cudaFuncSetAttribute(gemm_mma<false, KC>,      cudaFuncAttributeMaxDynamicSharedMemorySize, SMEM_DYN);
    cudaFuncSetAttribute(gemm_mma<true, 2 * CIN>,  cudaFuncAttributeMaxDynamicSharedMemorySize, SMEM_DYN);

    // 0) transpose feats into right half of concat buffer; transpose obj weights
    transpose_feats<<<dim3(HWSZ / 32, CIN / 32, NB), 256>>>(feats, cat);
    wtrans_kernel<<<dim3(CIN / 32, KC / 32), 256>>>(wo1, wo1t, KC, CIN);
    wtrans_kernel<<<dim3(CIN / 32, KC / 32), 256>>>(wd,  wdt,  KC, CIN);
    wtrans_kernel<<<dim3(KC / 32, KC / 32),  256>>>(wo2, wo2t, KC, KC);
    // 1) softmax over spatial
    softmax_p_kernel<<<NB * KCLS, 256>>>(probs, p);
    // 2) class-weighted pooling -> proxy
    proxy_kernel<<<NB * (CIN / 4), 256>>>(feats, p, proxy);
    // 3) object branch -> kk, val (transposed weights, coalesced)
    obj_kernel<<<NB * KCLS, 256>>>(proxy,
                                   wo1t, bo1, so1, to1,
                                   wo2t, bo2, so2, to2,
                                   wdt, bd, sd, td,
                                   kk, val);
    // 4) f_pixel stage 1: featsT -> q1
    gemm_mma<false, CIN><<<dim3(KC / 128, MTOT / 128), 256, SMEM_DYN>>>(
        cat + 512, wp1, bp1, sp1, tp1, buf1, KC, 1024, KC);
    // 5) f_pixel stage 2: q1 -> q
    gemm_mma<false, KC><<<dim3(KC / 128, MTOT / 128), 256, SMEM_DYN>>>(
        buf1, wp2, bp2, sp2, tp2, q, KC, KC, KC);
    // 6) attention: q, kk, val -> ctx (reuse buf1)
    attn_kernel<<<MTOT / 64, 256>>>(q, kk, val, buf1);
    // 7) f_up: ctx -> left half of concat buffer
    gemm_mma<false, KC><<<dim3(CIN / 128, MTOT / 128), 256, SMEM_DYN>>>(
        buf1, wu, bu, su, tu, cat, CIN, KC, 1024);
    // 8) final fusion: cat -> out (channel-major store)
    gemm_mma<true, 2 * CIN><<<dim3(OUTC / 128, MTOT / 128), 256, SMEM_DYN>>>(
        cat, wf, bf, sf, tf, out, OUTC, 1024, 0);
}

// round 6
// speedup vs baseline: 5.1850x; 1.2649x over previous
#include <cuda_runtime.h>
#include <cuda_bf16.h>
#include <cstdint>

// Problem constants
#define NB    4
#define CIN   512
#define HH    128
#define WW    128
#define HWSZ  16384
#define LOG2HW 14
#define KCLS  19
#define KC    256
#define OUTC  512
#define MTOT  (NB * HWSZ)   // 65536

// Scratch (device globals; no allocations allowed)
static __device__ float g_p[NB * KCLS * HWSZ];          // softmax probs
static __device__ float g_proxy[NB * CIN * KCLS];       // (n, c, k)
static __device__ float g_kk[NB * KC * KCLS];           // (n, kc, k)
static __device__ float g_val[NB * KCLS * KC];          // (n, k, kc)
static __device__ float g_buf1[(size_t)MTOT * KC];      // q1, then ctx   (m, kc)
static __device__ float g_q[(size_t)MTOT * KC];         // q              (m, kc)
static __device__ float g_cat[(size_t)MTOT * 1024];     // [ctx_up | featsT] (m, 1024)
static __device__ float g_wo1t[CIN * KC];               // wo1^T (c, o)
static __device__ float g_wdt[CIN * KC];                // wd^T  (c, o)
static __device__ float g_wo2t[KC * KC];                // wo2^T (c, o)
// tf32-pre-rounded weights for the 4 big GEMMs
static __device__ float g_w1r[KC * CIN];
static __device__ float g_w2r[KC * KC];
static __device__ float g_wur[CIN * KC];
static __device__ float g_wfr[OUTC * 2 * CIN];

__device__ __forceinline__ float relu_(float x) { return fmaxf(x, 0.0f); }

__device__ __forceinline__ uint32_t f2tf32(float x) {
    uint32_t r;
    asm("cvt.rna.tf32.f32 %0, %1;" : "=r"(r) : "f"(x));
    return r;
}
__device__ __forceinline__ float roundtf(float x) {
    return __uint_as_float(f2tf32(x));
}

__device__ __forceinline__ uint32_t smem_u32(const void* p) {
    uint32_t a;
    asm("{ .reg .u64 t; cvta.to.shared.u64 t, %1; cvt.u32.u64 %0, t; }" : "=r"(a) : "l"(p));
    return a;
}
__device__ __forceinline__ void cp16(uint32_t saddr, const void* g) {
    asm volatile("cp.async.cg.shared.global [%0], [%1], 16;" :: "r"(saddr), "l"(g));
}
#define CP_COMMIT() asm volatile("cp.async.commit_group;" ::: "memory")
#define CP_WAIT1()  asm volatile("cp.async.wait_group 1;" ::: "memory")

__device__ __forceinline__ void mma_tf32(float* c, const uint32_t* a,
                                         uint32_t b0, uint32_t b1) {
    asm volatile(
        "mma.sync.aligned.m16n8k8.row.col.f32.tf32.tf32.f32 "
        "{%0,%1,%2,%3}, {%4,%5,%6,%7}, {%8,%9}, {%0,%1,%2,%3};"
        : "+f"(c[0]), "+f"(c[1]), "+f"(c[2]), "+f"(c[3])
        : "r"(a[0]), "r"(a[1]), "r"(a[2]), "r"(a[3]), "r"(b0), "r"(b1));
}

// ---------------------------------------------------------------------------
// tf32 mma.sync GEMM with fused bias/BN/ReLU epilogue.
//   out = relu((A @ W^T + b) * s + t)
// Inputs A and W must be PRE-ROUNDED to tf32 (cvt.rna applied at producer).
// A row-major (M x KIN, leading dim lda). W row-major (Nout x KIN).
// Grid: (Nout/128, MTOT/128) -- o-tile fastest: co-resident CTAs share A in L2.
// CTA tile 128x128, K-chunk 32 (128B rows), 3-stage cp.async pipeline (96KB).
// 8 warps = 4(m) x 2(n); warp tile 32x64; fragment m16n8k8. 2 CTAs/SM.
// Smem: row r (32 floats), 16B-chunk j stored at chunk (j ^ (r&7)).
// ---------------------------------------------------------------------------
template<bool STORE_T, bool ROUND, int KIN>
__global__ __launch_bounds__(256, 2)
void gemm_mma(const float* __restrict__ A, const float* __restrict__ W,
              const float* __restrict__ bias, const float* __restrict__ sc,
              const float* __restrict__ sh, float* __restrict__ outp,
              int Nout, int lda, int ld_out)
{
    extern __shared__ __align__(16) float smem[];   // 3 * 8192 floats = 96KB

    int tid  = threadIdx.x;
    int wid  = tid >> 5;
    int lane = tid & 31;
    int warp_m = wid & 3;
    int warp_n = wid >> 2;
    int t4 = lane >> 2;
    int q  = lane & 3;

    int o0 = blockIdx.x * 128;
    int m0 = blockIdx.y * 128;

    uint32_t smb = smem_u32(smem);

    float acc[2][8][4];
#pragma unroll
    for (int mf = 0; mf < 2; mf++)
#pragma unroll
        for (int nf = 0; nf < 8; nf++)
#pragma unroll
            for (int e = 0; e < 4; e++) acc[mf][nf][e] = 0.0f;

    constexpr int nchunk = KIN >> 5;

    // thread -> 4 x (row, 16B-chunk) for the async copies; precompute byte offs
    uint32_t soff[4];
    uint32_t arow[4];
#pragma unroll
    for (int i = 0; i < 4; i++) {
        int idx = tid + (i << 8);
        int r = idx >> 3;
        int j = idx & 7;
        arow[i] = r;
        soff[i] = (uint32_t)(r * 128 + ((j ^ (r & 7)) << 4));
    }

    const float* Abase = A + (size_t)m0 * lda;
    const float* Bbase = W + (size_t)o0 * KIN;

    auto issue = [&](int ic) {
        int st = ic % 3;
        uint32_t sa = smb + (uint32_t)st * 32768u;
        uint32_t sb = sa + 16384u;
        const float* Ab = Abase + (ic << 5);
        const float* Bb = Bbase + (ic << 5);
#pragma unroll
        for (int i = 0; i < 4; i++) {
            int j4 = (tid + (i << 8)) & 7;
            cp16(sa + soff[i], Ab + (size_t)arow[i] * lda + (j4 << 2));
            cp16(sb + soff[i], Bb + (size_t)arow[i] * KIN + (j4 << 2));
        }
    };
    auto compute = [&](int st) {
        const float* sa = smem + st * 8192;
        const float* sb = sa + 4096;
        int r0b = warp_m * 32 + t4;
        int rm  = t4;
        int rnb = warp_n * 64 + t4;
#pragma unroll
        for (int ks = 0; ks < 4; ks++) {
            int c0 = ((2 * ks) ^ rm) << 2;
            int c1 = ((2 * ks + 1) ^ rm) << 2;
            uint32_t a[2][4];
#pragma unroll
            for (int mf = 0; mf < 2; mf++) {
                int r0 = r0b + mf * 16;
                int r1 = r0 + 8;
                a[mf][0] = __float_as_uint(sa[(r0 << 5) + c0 + q]);
                a[mf][1] = __float_as_uint(sa[(r1 << 5) + c0 + q]);
                a[mf][2] = __float_as_uint(sa[(r0 << 5) + c1 + q]);
                a[mf][3] = __float_as_uint(sa[(r1 << 5) + c1 + q]);
            }
#pragma unroll
            for (int nf = 0; nf < 8; nf++) {
                int rn = rnb + nf * 8;
                uint32_t b0 = __float_as_uint(sb[(rn << 5) + c0 + q]);
                uint32_t b1 = __float_as_uint(sb[(rn << 5) + c1 + q]);
                mma_tf32(acc[0][nf], a[0], b0, b1);
                mma_tf32(acc[1][nf], a[1], b0, b1);
            }
        }
    };

    issue(0); CP_COMMIT();
    issue(1); CP_COMMIT();
    for (int ic = 0; ic < nchunk; ic++) {
        CP_WAIT1();
        __syncthreads();
        if (ic + 2 < nchunk) issue(ic + 2);
        CP_COMMIT();
        compute(ic % 3);
    }

    // Epilogue
    int ob = o0 + warp_n * 64;
    float al[16], be[16];
#pragma unroll
    for (int nf = 0; nf < 8; nf++)
#pragma unroll
        for (int e = 0; e < 2; e++) {
            int o = ob + nf * 8 + 2 * q + e;
            float sv = sc[o];
            al[nf * 2 + e] = sv;
            be[nf * 2 + e] = bias[o] * sv + sh[o];
        }

    if (!STORE_T) {
#pragma unroll
        for (int mf = 0; mf < 2; mf++)
#pragma unroll
            for (int h = 0; h < 2; h++) {
                int m = m0 + warp_m * 32 + mf * 16 + t4 + h * 8;
                float* orow = outp + (size_t)m * ld_out;
#pragma unroll
                for (int nf = 0; nf < 8; nf++) {
                    int n = ob + nf * 8 + 2 * q;
                    float2 v;
                    v.x = relu_(acc[mf][nf][h * 2 + 0] * al[nf * 2 + 0] + be[nf * 2 + 0]);
                    v.y = relu_(acc[mf][nf][h * 2 + 1] * al[nf * 2 + 1] + be[nf * 2 + 1]);
                    if (ROUND) { v.x = roundtf(v.x); v.y = roundtf(v.y); }
                    *(float2*)(orow + n) = v;
                }
            }
    } else {
#pragma unroll
        for (int mf = 0; mf < 2; mf++)
#pragma unroll
            for (int h = 0; h < 2; h++) {
                int m = m0 + warp_m * 32 + mf * 16 + t4 + h * 8;
                int nb = m >> LOG2HW;
                int s  = m & (HWSZ - 1);
                float* obase = outp + (size_t)nb * Nout * HWSZ + s;
#pragma unroll
                for (int nf = 0; nf < 8; nf++) {
                    int o = ob + nf * 8 + 2 * q;
                    float v0 = relu_(acc[mf][nf][h * 2 + 0] * al[nf * 2 + 0] + be[nf * 2 + 0]);
                    float v1 = relu_(acc[mf][nf][h * 2 + 1] * al[nf * 2 + 1] + be[nf * 2 + 1]);
                    if (ROUND) { v0 = roundtf(v0); v1 = roundtf(v1); }
                    obase[(size_t)o * HWSZ] = v0;
                    obase[(size_t)(o + 1) * HWSZ] = v1;
                }
            }
    }
}

// ---------------------------------------------------------------------------
// Transpose feats (n,c,s) into the right half of g_cat (tf32-rounded).
// ---------------------------------------------------------------------------
__global__ __launch_bounds__(256)
void transpose_feats(const float* __restrict__ feats, float* __restrict__ cat)
{
    __shared__ float t[32][33];
    int sb = blockIdx.x * 32;
    int cb = blockIdx.y * 32;
    int n  = blockIdx.z;
    int tx = threadIdx.x & 31, ty = threadIdx.x >> 5;
    const float* fb = feats + ((size_t)n * CIN + cb) * HWSZ + sb;
#pragma unroll
    for (int j = 0; j < 4; j++)
        t[ty + j * 8][tx] = fb[(size_t)(ty + j * 8) * HWSZ + tx];
    __syncthreads();
    float* ob = cat + ((size_t)(n * HWSZ + sb)) * 1024 + 512 + cb;
#pragma unroll
    for (int j = 0; j < 4; j++)
        ob[(size_t)(ty + j * 8) * 1024 + tx] = roundtf(t[tx][ty + j * 8]);
}

// ---------------------------------------------------------------------------
// Small weight transpose: out[c * O + o] = in[o * C + c].
// ---------------------------------------------------------------------------
__global__ __launch_bounds__(256)
void wtrans_kernel(const float* __restrict__ in, float* __restrict__ out,
                   int O, int C)
{
    __shared__ float t[32][33];
    int cb = blockIdx.x * 32;
    int ob = blockIdx.y * 32;
    int tx = threadIdx.x & 31, ty = threadIdx.x >> 5;
#pragma unroll
    for (int j = 0; j < 4; j++)
        t[ty + j * 8][tx] = in[(size_t)(ob + ty + j * 8) * C + cb + tx];
    __syncthreads();
#pragma unroll
    for (int j = 0; j < 4; j++)
        out[(size_t)(cb + ty + j * 8) * O + ob + tx] = t[tx][ty + j * 8];
}

// ---------------------------------------------------------------------------
// Elementwise tf32 rounding (for GEMM weights).
// ---------------------------------------------------------------------------
__global__ __launch_bounds__(256)
void wround_kernel(const float* __restrict__ in, float* __restrict__ out, int n)
{
    int i = blockIdx.x * 1024 + threadIdx.x * 4;
    if (i < n) {
        float4 v = *(const float4*)(in + i);
        v.x = roundtf(v.x); v.y = roundtf(v.y);
        v.z = roundtf(v.z); v.w = roundtf(v.w);
        *(float4*)(out + i) = v;
    }
}

// ---------------------------------------------------------------------------
// softmax of probs over spatial dim. One block per (n,k) row.
// ---------------------------------------------------------------------------
__global__ __launch_bounds__(256)
void softmax_p_kernel(const float* __restrict__ probs, float* __restrict__ p)
{
    int row = blockIdx.x;
    const float* src = probs + (size_t)row * HWSZ;
    float*       dst = p     + (size_t)row * HWSZ;
    int tid = threadIdx.x;
    __shared__ float red[256];

    float m = -1e30f;
    for (int i = tid; i < HWSZ; i += 256) m = fmaxf(m, src[i]);
    red[tid] = m; __syncthreads();
    for (int s = 128; s > 0; s >>= 1) {
        if (tid < s) red[tid] = fmaxf(red[tid], red[tid + s]);
        __syncthreads();
    }
    m = red[0]; __syncthreads();

    float sum = 0.0f;
    for (int i = tid; i < HWSZ; i += 256) sum += __expf(src[i] - m);
    red[tid] = sum; __syncthreads();
    for (int s = 128; s > 0; s >>= 1) {
        if (tid < s) red[tid] += red[tid + s];
        __syncthreads();
    }
    float inv = 1.0f / red[0];

    for (int i = tid; i < HWSZ; i += 256) dst[i] = __expf(src[i] - m) * inv;
}

// ---------------------------------------------------------------------------
// proxy[n,c,k] = sum_s p[n,k,s] * feats[n,c,s].
// ---------------------------------------------------------------------------
__global__ __launch_bounds__(256)
void proxy_kernel(const float* __restrict__ feats, const float* __restrict__ p,
                  float* __restrict__ proxy)
{
    int b  = blockIdx.x;
    int n  = b / (CIN / 4);
    int c0 = (b % (CIN / 4)) * 4;
    int tid = threadIdx.x;

    float acc[4][KCLS];
#pragma unroll
    for (int cc = 0; cc < 4; cc++)
#pragma unroll
        for (int k = 0; k < KCLS; k++) acc[cc][k] = 0.0f;

    const float* pb = p     + (size_t)n * KCLS * HWSZ;
    const float* fb = feats + ((size_t)n * CIN + c0) * HWSZ;

    for (int s = tid; s < HWSZ; s += 256) {
        float pv[KCLS];
#pragma unroll
        for (int k = 0; k < KCLS; k++) pv[k] = pb[k * HWSZ + s];
#pragma unroll
        for (int cc = 0; cc < 4; cc++) {
            float f = fb[cc * HWSZ + s];
#pragma unroll
            for (int k = 0; k < KCLS; k++) acc[cc][k] += f * pv[k];
        }
    }

    __shared__ float red[8][80];
    int lane = tid & 31, wp = tid >> 5;
#pragma unroll
    for (int cc = 0; cc < 4; cc++)
#pragma unroll
        for (int k = 0; k < KCLS; k++) {
            float v = acc[cc][k];
            v += __shfl_down_sync(0xffffffffu, v, 16);
            v += __shfl_down_sync(0xffffffffu, v, 8);
            v += __shfl_down_sync(0xffffffffu, v, 4);
            v += __shfl_down_sync(0xffffffffu, v, 2);
            v += __shfl_down_sync(0xffffffffu, v, 1);
            if (lane == 0) red[wp][cc * KCLS + k] = v;
        }
    __syncthreads();
    if (tid < 4 * KCLS) {
        float s2 = 0.0f;
#pragma unroll
        for (int w2 = 0; w2 < 8; w2++) s2 += red[w2][tid];
        int cc = tid / KCLS, k = tid % KCLS;
        proxy[((size_t)n * CIN + c0 + cc) * KCLS + k] = s2;
    }
}

// ---------------------------------------------------------------------------
// Object branch with transposed weights: one block per (n,k).
// ---------------------------------------------------------------------------
__global__ __launch_bounds__(256)
void obj_kernel(const float* __restrict__ proxy,
                const float* __restrict__ wo1t, const float* __restrict__ bo1,
                const float* __restrict__ so1, const float* __restrict__ to1,
                const float* __restrict__ wo2t, const float* __restrict__ bo2,
                const float* __restrict__ so2, const float* __restrict__ to2,
                const float* __restrict__ wdt,  const float* __restrict__ bd,
                const float* __restrict__ sd,  const float* __restrict__ td,
                float* __restrict__ kkout, float* __restrict__ valout)
{
    int n = blockIdx.x / KCLS, k = blockIdx.x % KCLS;
    int tid = threadIdx.x;
    __shared__ float col[CIN];
    __shared__ float h1[KC];

    const float* pc = proxy + (size_t)n * CIN * KCLS + k;
    col[tid]       = pc[(size_t)tid * KCLS];
    col[tid + 256] = pc[(size_t)(tid + 256) * KCLS];
    __syncthreads();

    float a1 = 0.0f, av = 0.0f;
#pragma unroll 8
    for (int c = 0; c < CIN; c++) {
        float x = col[c];
        a1 += x * wo1t[c * KC + tid];
        av += x * wdt[c * KC + tid];
    }
    a1 = relu_((a1 + bo1[tid]) * so1[tid] + to1[tid]);
    av = relu_((av + bd[tid])  * sd[tid]  + td[tid]);
    valout[((size_t)n * KCLS + k) * KC + tid] = av;
    h1[tid] = a1;
    __syncthreads();

    float a2 = 0.0f;
#pragma unroll 8
    for (int c = 0; c < KC; c++) a2 += h1[c] * wo2t[c * KC + tid];
    a2 = relu_((a2 + bo2[tid]) * so2[tid] + to2[tid]);
    kkout[((size_t)n * KC + tid) * KCLS + k] = a2;
}

// ---------------------------------------------------------------------------
// Attention: logits(64x19) -> softmax -> ctx(64x256) tf32-rounded.
// ---------------------------------------------------------------------------
__global__ __launch_bounds__(256)
void attn_kernel(const float* __restrict__ q, const float* __restrict__ kk,
                 const float* __restrict__ val, float* __restrict__ ctx)
{
    int m0 = blockIdx.x * 64;
    int n  = m0 >> LOG2HW;
    int tid = threadIdx.x;

    __shared__ float kks[KC][KCLS];
    __shared__ float qs[64][33];
    __shared__ float sims[64][20];

    const float* kkb = kk + (size_t)n * KC * KCLS;
    for (int i = tid; i < KC * KCLS; i += 256) {
        kks[i / KCLS][i % KCLS] = kkb[i];
    }
    __syncthreads();

    int i = tid & 63;
    int g = tid >> 6;
    float acc[5];
#pragma unroll
    for (int z = 0; z < 5; z++) acc[z] = 0.0f;

    for (int kc0 = 0; kc0 < KC; kc0 += 32) {
        int r  = tid >> 3;
        int c4 = (tid & 7) * 4;
#pragma unroll
        for (int rr = 0; rr < 2; rr++) {
            float4 v = *(const float4*)&q[(size_t)(m0 + r + rr * 32) * KC + kc0 + c4];
            qs[r + rr * 32][c4 + 0] = v.x;
            qs[r + rr * 32][c4 + 1] = v.y;
            qs[r + rr * 32][c4 + 2] = v.z;
            qs[r + rr * 32][c4 + 3] = v.w;
        }
        __syncthreads();
#pragma unroll 8
        for (int kc = 0; kc < 32; kc++) {
            float a = qs[i][kc];
#pragma unroll
            for (int z = 0; z < 5; z++) {
                int k = g + z * 4;
                if (k < KCLS) acc[z] += a * kks[kc0 + kc][k];
            }
        }
        __syncthreads();
    }

#pragma unroll
    for (int z = 0; z < 5; z++) {
        int k = g + z * 4;
        if (k < KCLS) sims[i][k] = acc[z] * 0.0625f;
    }
    __syncthreads();

    if (tid < 64) {
        float m = -1e30f;
#pragma unroll
        for (int k = 0; k < KCLS; k++) m = fmaxf(m, sims[tid][k]);
        float s = 0.0f;
        float e[KCLS];
#pragma unroll
        for (int k = 0; k < KCLS; k++) { e[k] = __expf(sims[tid][k] - m); s += e[k]; }
        float inv = 1.0f / s;
#pragma unroll
        for (int k = 0; k < KCLS; k++) sims[tid][k] = e[k] * inv;
    }
    __syncthreads();

    float vreg[KCLS];
    const float* vb = val + (size_t)n * KCLS * KC + tid;
#pragma unroll
    for (int k = 0; k < KCLS; k++) vreg[k] = vb[k * KC];

    for (int ii = 0; ii < 64; ii++) {
        float a = 0.0f;
#pragma unroll
        for (int k = 0; k < KCLS; k++) a += sims[ii][k] * vreg[k];
        ctx[(size_t)(m0 + ii) * KC + tid] = roundtf(a);
    }
}

// ---------------------------------------------------------------------------
extern "C" void kernel_launch(void* const* d_in, const int* in_sizes, int n_in,
                              void* d_out, int out_size)
{
    const float* feats = (const float*)d_in[0];
    const float* probs = (const float*)d_in[1];
    const float* wp1 = (const float*)d_in[2];
    const float* bp1 = (const float*)d_in[3];
    const float* sp1 = (const float*)d_in[4];
    const float* tp1 = (const float*)d_in[5];
    const float* wp2 = (const float*)d_in[6];
    const float* bp2 = (const float*)d_in[7];
    const float* sp2 = (const float*)d_in[8];
    const float* tp2 = (const float*)d_in[9];
    const float* wo1 = (const float*)d_in[10];
    const float* bo1 = (const float*)d_in[11];
    const float* so1 = (const float*)d_in[12];
    const float* to1 = (const float*)d_in[13];
    const float* wo2 = (const float*)d_in[14];
    const float* bo2 = (const float*)d_in[15];
    const float* so2 = (const float*)d_in[16];
    const float* to2 = (const float*)d_in[17];
    const float* wd  = (const float*)d_in[18];
    const float* bd  = (const float*)d_in[19];
    const float* sd  = (const float*)d_in[20];
    const float* td  = (const float*)d_in[21];
    const float* wu  = (const float*)d_in[22];
    const float* bu  = (const float*)d_in[23];
    const float* su  = (const float*)d_in[24];
    const float* tu  = (const float*)d_in[25];
    const float* wf  = (const float*)d_in[26];
    const float* bf  = (const float*)d_in[27];
    const float* sf  = (const float*)d_in[28];
    const float* tf  = (const float*)d_in[29];

    float *p, *proxy, *kk, *val, *buf1, *q, *cat, *wo1t, *wdt, *wo2t;
    float *w1r, *w2r, *wur, *wfr;
    cudaGetSymbolAddress((void**)&p,     g_p);
    cudaGetSymbolAddress((void**)&proxy, g_proxy);
    cudaGetSymbolAddress((void**)&kk,    g_kk);
    cudaGetSymbolAddress((void**)&val,   g_val);
    cudaGetSymbolAddress((void**)&buf1,  g_buf1);
    cudaGetSymbolAddress((void**)&q,     g_q);
    cudaGetSymbolAddress((void**)&cat,   g_cat);
    cudaGetSymbolAddress((void**)&wo1t,  g_wo1t);
    cudaGetSymbolAddress((void**)&wdt,   g_wdt);
    cudaGetSymbolAddress((void**)&wo2t,  g_wo2t);
    cudaGetSymbolAddress((void**)&w1r,   g_w1r);
    cudaGetSymbolAddress((void**)&w2r,   g_w2r);
    cudaGetSymbolAddress((void**)&wur,   g_wur);
    cudaGetSymbolAddress((void**)&wfr,   g_wfr);

    float* out = (float*)d_out;

    const int SMEM_DYN = 3 * 8192 * 4;   // 96KB: 3-stage A+B tiles
    cudaFuncSetAttribute(gemm_mma<false, true,  CIN>,    cudaFuncAttributeMaxDynamicSharedMemorySize, SMEM_DYN);
    cudaFuncSetAttribute(gemm_mma<false, false, KC>,     cudaFuncAttributeMaxDynamicSharedMemorySize, SMEM_DYN);
    cudaFuncSetAttribute(gemm_mma<false, true,  KC>,     cudaFuncAttributeMaxDynamicSharedMemorySize, SMEM_DYN);
    cudaFuncSetAttribute(gemm_mma<true,  false, 2*CIN>,  cudaFuncAttributeMaxDynamicSharedMemorySize, SMEM_DYN);

    // 0) layout prep: feats transpose (rounded), obj weight transposes,
    //    tf32 rounding of the 4 GEMM weights
    transpose_feats<<<dim3(HWSZ / 32, CIN / 32, NB), 256>>>(feats, cat);
    wtrans_kernel<<<dim3(CIN / 32, KC / 32), 256>>>(wo1, wo1t, KC, CIN);
    wtrans_kernel<<<dim3(CIN / 32, KC / 32), 256>>>(wd,  wdt,  KC, CIN);
    wtrans_kernel<<<dim3(KC / 32, KC / 32),  256>>>(wo2, wo2t, KC, KC);
    wround_kernel<<<(KC * CIN) / 1024, 256>>>(wp1, w1r, KC * CIN);
    wround_kernel<<<(KC * KC) / 1024, 256>>>(wp2, w2r, KC * KC);
    wround_kernel<<<(CIN * KC) / 1024, 256>>>(wu, wur, CIN * KC);
    wround_kernel<<<(OUTC * 2 * CIN) / 1024, 256>>>(wf, wfr, OUTC * 2 * CIN);
    // 1) softmax over spatial
    softmax_p_kernel<<<NB * KCLS, 256>>>(probs, p);
    // 2) class-weighted pooling -> proxy
    proxy_kernel<<<NB * (CIN / 4), 256>>>(feats, p, proxy);
    // 3) object branch -> kk, val
    obj_kernel<<<NB * KCLS, 256>>>(proxy,
                                   wo1t, bo1, so1, to1,
                                   wo2t, bo2, so2, to2,
                                   wdt, bd, sd, td,
                                   kk, val);
    // 4) f_pixel stage 1: featsT -> q1 (rounded for G2)
    gemm_mma<false, true, CIN><<<dim3(KC / 128, MTOT / 128), 256, SMEM_DYN>>>(
        cat + 512, w1r, bp1, sp1, tp1, buf1, KC, 1024, KC);
    // 5) f_pixel stage 2: q1 -> q (consumed by fp32 attn; no rounding)
    gemm_mma<false, false, KC><<<dim3(KC / 128, MTOT / 128), 256, SMEM_DYN>>>(
        buf1, w2r, bp2, sp2, tp2, q, KC, KC, KC);
    // 6) attention: q, kk, val -> ctx (rounded, reuse buf1)
    attn_kernel<<<MTOT / 64, 256>>>(q, kk, val, buf1);
    // 7) f_up: ctx -> left half of concat buffer (rounded for G4)
    gemm_mma<false, true, KC><<<dim3(CIN / 128, MTOT / 128), 256, SMEM_DYN>>>(
        buf1, wur, bu, su, tu, cat, CIN, KC, 1024);
    // 8) final fusion: cat -> out (channel-major store)
    gemm_mma<true, false, 2 * CIN><<<dim3(OUTC / 128, MTOT / 128), 256, SMEM_DYN>>>(
        cat, wfr, bf, sf, tf, out, OUTC, 1024, 0);
}